// round 9
// baseline (speedup 1.0000x reference)
#include <cuda_runtime.h>
#include <math.h>

#define N 4096
#define NTHREADS 1024
#define NCTA_ROW 64
#define SLICE 64
#define NCHUNK 64
#define CHUNK 64
#define NBINS 8192
#define BSHIFT 19          // bucket = enc >> 19  (top 13 bits)

typedef unsigned long long u64;
typedef unsigned int u32;

__device__ u64   g_keys[2][N];
__device__ float g_rank[2][N];
__device__ float g_sum[2], g_sumsq[2], g_bce;
__device__ u32   g_tick[2][N];     // duplicate-value tickets (reset by finisher)
__device__ u32   g_cnt[2];
__device__ u32   g_cnt2;

// ---- float -> order-preserving uint (ascending), exact inverse ----
__device__ __forceinline__ u32 encodeVal(float v) {
    u32 b = __float_as_uint(v);
    return (b & 0x80000000u) ? ~b : (b | 0x80000000u);
}
__device__ __forceinline__ float decodeVal(u32 e) {
    return (e & 0x80000000u) ? __uint_as_float(e ^ 0x80000000u)
                             : __uint_as_float(~e);
}

__device__ __forceinline__ uint4 packAtom(float S, float W, float C, int st) {
    uint4 a;
    a.x = __float_as_uint(S); a.y = __float_as_uint(W);
    a.z = __float_as_uint(C); a.w = (u32)st;
    return a;
}

__device__ __forceinline__ float blockReduceSum(float v, float* scratch) {
#pragma unroll
    for (int o = 16; o; o >>= 1) v += __shfl_down_sync(0xffffffffu, v, o);
    int w = threadIdx.x >> 5, l = threadIdx.x & 31;
    __syncthreads();
    if (l == 0) scratch[w] = v;
    __syncthreads();
    if (w == 0) {
        float t = scratch[l];   // exactly 32 warps
#pragma unroll
        for (int o = 16; o; o >>= 1) t += __shfl_down_sync(0xffffffffu, t, o);
        if (l == 0) scratch[0] = t;
    }
    __syncthreads();
    return scratch[0];
}

// ---- SMEM byte offsets (tail layout identical to R8; counting overlays) ----
#define SM_KARR   0                     // u64[4096] 32768   | counting: u32 enc[4096] (16KB)
#define SM_STK    32768                 // uint4[4096] 65536 | counting: scanHist u32[8192] (32KB)
#define SM_DENSE  98304                 // uint4[4096] 65536 | counting: sorted u32[4096] (16KB)
#define SM_FSTART 163840                // int[4097]
#define SM_FMEAN  180228                // float[4096]
#define SM_CNT    196612                // int[64]
#define SM_OFF    196868                // int[64]
#define SM_RED    197124                // float[32] / u32 wTot[32]
#define SM_WHO    197252                // u32[2]
#define SM_NB     197260                // int
#define SMEM_BYTES 197280

__global__ __launch_bounds__(NTHREADS, 1)
void fusedKernel(const float* __restrict__ yhat,
                 const float* __restrict__ ytar,
                 float* __restrict__ out) {
    extern __shared__ char sm[];
    u64*   kArr   = (u64*)(sm + SM_KARR);
    u32*   encArr = (u32*)(sm + SM_KARR);     // counting overlay
    uint4* stk    = (uint4*)(sm + SM_STK);
    u32*   scanH  = (u32*)(sm + SM_STK);      // counting overlay: 8192 bins
    uint4* dense  = (uint4*)(sm + SM_DENSE);
    u32*   sorted = (u32*)(sm + SM_DENSE);    // counting overlay: bucket-sorted encs
    float* rLoc   = (float*)(sm + SM_FMEAN);  // tail overlay for ranks (scatter phase)
    int*   fStart = (int*)(sm + SM_FSTART);
    float* fMean  = (float*)(sm + SM_FMEAN);
    int*   cntArr = (int*)(sm + SM_CNT);
    int*   offArr = (int*)(sm + SM_OFF);
    float* red    = (float*)(sm + SM_RED);
    u32*   wTot   = (u32*)(sm + SM_RED);
    u32*   shWho  = (u32*)(sm + SM_WHO);
    int*   nbPtr  = (int*)(sm + SM_NB);

    const int tid  = threadIdx.x;
    const int lane = tid & 31;
    const int wrp  = tid >> 5;
    const int row  = blockIdx.x >> 6;
    const int ctaSlot = blockIdx.x & (NCTA_ROW - 1);
    const float* src = row ? ytar : yhat;

    // ============ Phase 1: bucket-ranking (all 128 CTAs) ============
    uint4 e4;
    {
        float4 v = ((const float4*)src)[tid];
        e4.x = encodeVal(v.x); e4.y = encodeVal(v.y);
        e4.z = encodeVal(v.z); e4.w = encodeVal(v.w);
        ((uint4*)encArr)[tid] = e4;
        uint4 z = make_uint4(0, 0, 0, 0);
        ((uint4*)scanH)[2 * tid]     = z;       // zero 8192 bins
        ((uint4*)scanH)[2 * tid + 1] = z;
    }
    __syncthreads();

    // histogram (13-bit buckets)
    atomicAdd(&scanH[e4.x >> BSHIFT], 1u);
    atomicAdd(&scanH[e4.y >> BSHIFT], 1u);
    atomicAdd(&scanH[e4.z >> BSHIFT], 1u);
    atomicAdd(&scanH[e4.w >> BSHIFT], 1u);
    __syncthreads();

    // exclusive scan of 8192 bins (8 per thread + block scan)
    {
        uint4 lo = ((uint4*)scanH)[2 * tid];
        uint4 hi = ((uint4*)scanH)[2 * tid + 1];
        u32 c0 = lo.x, c1 = lo.y, c2 = lo.z, c3 = lo.w;
        u32 c4 = hi.x, c5 = hi.y, c6 = hi.z, c7 = hi.w;
        u32 sum = c0 + c1 + c2 + c3 + c4 + c5 + c6 + c7;

        u32 x = sum;                       // warp inclusive scan
#pragma unroll
        for (int o = 1; o < 32; o <<= 1) {
            u32 y = __shfl_up_sync(0xffffffffu, x, o);
            if (lane >= o) x += y;
        }
        if (lane == 31) wTot[wrp] = x;
        __syncthreads();
        if (wrp == 0) {
            u32 t = wTot[lane];
#pragma unroll
            for (int o = 1; o < 32; o <<= 1) {
                u32 y = __shfl_up_sync(0xffffffffu, t, o);
                if (lane >= o) t += y;
            }
            wTot[lane] = t;                // inclusive warp totals
        }
        __syncthreads();
        u32 base = (wrp ? wTot[wrp - 1] : 0u) + (x - sum);  // thread-exclusive

        uint4 olo, ohi;
        olo.x = base;
        olo.y = olo.x + c0; olo.z = olo.y + c1; olo.w = olo.z + c2;
        ohi.x = olo.w + c3; ohi.y = ohi.x + c4; ohi.z = ohi.y + c5; ohi.w = ohi.z + c6;
        ((uint4*)scanH)[2 * tid]     = olo;
        ((uint4*)scanH)[2 * tid + 1] = ohi;
    }
    __syncthreads();

    // counting-sort scatter: atomicAdd turns exclusive scan into inclusive
    {
        u32 s;
        s = atomicAdd(&scanH[e4.x >> BSHIFT], 1u); sorted[s] = e4.x;
        s = atomicAdd(&scanH[e4.y >> BSHIFT], 1u); sorted[s] = e4.y;
        s = atomicAdd(&scanH[e4.z >> BSHIFT], 1u); sorted[s] = e4.z;
        s = atomicAdd(&scanH[e4.w >> BSHIFT], 1u); sorted[s] = e4.w;
    }
    __syncthreads();
    // now scanH[b] == inclusive count (end of bucket b)

    // per-element exact position: this CTA's 64 elements, 16 threads each
    {
        const int p  = tid & 15;
        const int i  = ctaSlot * SLICE + (tid >> 4);
        const u32 en = encArr[i];
        const int b  = (int)(en >> BSHIFT);
        const int s1 = (int)scanH[b];
        const int s0 = b ? (int)scanH[b - 1] : 0;
        u32 c = 0;
        for (int j = s0 + p; j < s1; j += 16)
            c += (u32)(sorted[j] > en);
        u32 within = __reduce_add_sync(0xFFFFu << (lane & 16), c);
        if (p == 0) {
            u32 pos0 = (u32)(N - s1) + within;          // # strictly greater
            u32 tick = atomicAdd(&g_tick[row][pos0], 1u); // dedupe exact ties
            g_keys[row][pos0 + tick] = ((u64)en << 32) | (u32)i;
        }
    }

    // ============ gate 1: last CTA per row continues; rest exit ============
    __threadfence();
    __syncthreads();
    if (tid == 0) shWho[0] = atomicAdd(&g_cnt[row], 1);
    __syncthreads();
    if (shWho[0] != NCTA_ROW - 1) return;
    __threadfence();   // acquire other CTAs' g_keys writes

    // ============ Phase 2: PAV (1 CTA per row) ============
    {
        const u64* gk = g_keys[row];
#pragma unroll
        for (int m = 0; m < 4; m++) {
            int i = tid + m * NTHREADS;
            kArr[i] = gk[i];
        }
    }
    __syncthreads();

    // per-chunk PAV, all-float block state (exact: |sumW| < 2^24)
    if (tid < NCHUNK) {
        const int base = tid * CHUNK;
        float w  = (float)(N - base);            // w(i) = N - i, running
        float tS = decodeVal((u32)(kArr[base] >> 32));
        float tW = w, tC = 1.f;
        float tNum = tS - tW;
        int   tSt = base, sp = 0;
        for (int i = base + 1; i < base + CHUNK; ++i) {
            w -= 1.f;
            float s = decodeVal((u32)(kArr[i] >> 32));
            float cS = s, cW = w, cC = 1.f, cNum = s - w;
            int   cSt = i;
            while (tNum * cC < cNum * tC) {      // pool
                cS += tS; cW += tW; cC += tC; cSt = tSt;
                cNum = cS - cW;
                if (sp == 0) { tC = 0.f; break; }
                sp--;
                uint4 a = stk[base + sp];
                tS = __uint_as_float(a.x); tW = __uint_as_float(a.y);
                tC = __uint_as_float(a.z); tSt = (int)a.w;
                tNum = tS - tW;
            }
            if (tC > 0.f) { stk[base + sp] = packAtom(tS, tW, tC, tSt); sp++; }
            tS = cS; tW = cW; tC = cC; tSt = cSt; tNum = cNum;
        }
        stk[base + sp] = packAtom(tS, tW, tC, tSt); sp++;
        cntArr[tid] = sp;
    }
    __syncthreads();

    if (tid < NCHUNK) {
        int o = 0;
        for (int j = 0; j < tid; j++) o += cntArr[j];
        offArr[tid] = o;
    }
    __syncthreads();

    if (tid < NCHUNK) {
        int o = offArr[tid], c = cntArr[tid];
        for (int b = 0; b < c; b++) dense[o + b] = stk[tid * CHUNK + b];
    }
    __syncthreads();

    const int natoms = offArr[NCHUNK - 1] + cntArr[NCHUNK - 1];

    if (tid == 0) {
        uint4 a0 = dense[0];
        float tS = __uint_as_float(a0.x), tW = __uint_as_float(a0.y);
        float tC = __uint_as_float(a0.z);
        int   tSt = (int)a0.w;
        float tNum = tS - tW;
        int sp = 0;
        uint4 nxt = dense[(natoms > 1) ? 1 : 0];
        for (int t = 1; t < natoms; ++t) {
            uint4 a = nxt;
            nxt = dense[(t + 1 < natoms) ? (t + 1) : t];   // prefetch
            float cS = __uint_as_float(a.x), cW = __uint_as_float(a.y);
            float cC = __uint_as_float(a.z);
            int   cSt = (int)a.w;
            float cNum = cS - cW;
            while (tNum * cC < cNum * tC) {
                cS += tS; cW += tW; cC += tC; cSt = tSt;
                cNum = cS - cW;
                if (sp == 0) { tC = 0.f; break; }
                sp--;
                uint4 p = stk[sp];
                tS = __uint_as_float(p.x); tW = __uint_as_float(p.y);
                tC = __uint_as_float(p.z); tSt = (int)p.w;
                tNum = tS - tW;
            }
            if (tC > 0.f) { stk[sp] = packAtom(tS, tW, tC, tSt); sp++; }
            tS = cS; tW = cW; tC = cC; tSt = cSt; tNum = cNum;
        }
        stk[sp] = packAtom(tS, tW, tC, tSt); sp++;
        *nbPtr = sp;
    }
    __syncthreads();

    const int nb = *nbPtr;
    for (int b = tid; b < nb; b += NTHREADS) {
        uint4 a = stk[b];
        fStart[b] = (int)a.w;
        fMean[b]  = (__uint_as_float(a.x) - __uint_as_float(a.y))
                    / __uint_as_float(a.z);
    }
    if (tid == 0) fStart[nb] = N;
    __syncthreads();

    // ---- scatter + own-row moments ----
    // NOTE: fMean/rLoc share SMEM; read fMean for all 4 elements before any
    // rLoc write could clobber (ranks scattered to id, means indexed by lo).
    float sR = 0.f, sR2 = 0.f;
    float rv[4]; int idv[4];
#pragma unroll
    for (int m = 0; m < 4; m++) {
        int i = tid + m * NTHREADS;
        u64 kk = kArr[i];
        float s = decodeVal((u32)(kk >> 32));
        idv[m] = (int)(kk & 0xFFFFFFFFu);
        int lo = 0, hi = nb - 1;
        while (lo < hi) {
            int mid = (lo + hi + 1) >> 1;
            if (fStart[mid] <= lo + hi - lo, fStart[mid] <= i) lo = mid; else hi = mid - 1;
        }
        rv[m] = s - fMean[lo] - 2048.5f;     // shift is Spearman-invariant
    }
    __syncthreads();                          // all fMean reads done before rLoc writes
#pragma unroll
    for (int m = 0; m < 4; m++) {
        g_rank[row][idv[m]] = rv[m];
        rLoc[idv[m]] = rv[m];
        sR  += rv[m];
        sR2 += rv[m] * rv[m];
    }
    float S  = blockReduceSum(sR, red);
    float S2 = blockReduceSum(sR2, red);

    float B = 0.f;
    if (row == 1) {
        float4 x4 = ((const float4*)yhat)[tid];
        float4 y4 = ((const float4*)ytar)[tid];
        float sb = 0.f;
        sb += fmaxf(x4.x, 0.f) + log1pf(expf(-fabsf(x4.x))) - x4.x * y4.x;
        sb += fmaxf(x4.y, 0.f) + log1pf(expf(-fabsf(x4.y))) - x4.y * y4.y;
        sb += fmaxf(x4.z, 0.f) + log1pf(expf(-fabsf(x4.z))) - x4.z * y4.z;
        sb += fmaxf(x4.w, 0.f) + log1pf(expf(-fabsf(x4.w))) - x4.w * y4.w;
        B = blockReduceSum(sb, red);
    }
    if (tid == 0) {
        g_sum[row]   = S;
        g_sumsq[row] = S2;
        if (row == 1) g_bce = B;
    }

    // ============ gate 2: second of the two row CTAs finishes ============
    __threadfence();
    __syncthreads();
    if (tid == 0) shWho[1] = atomicAdd(&g_cnt2, 1);
    __syncthreads();
    if (shWho[1] != 1) return;
    __threadfence();   // acquire other row's ranks + partials

    {
        const float* other = g_rank[1 - row];
        float cr = 0.f;
#pragma unroll
        for (int m = 0; m < 4; m++) {
            int i = tid + m * NTHREADS;
            cr += other[i] * rLoc[i];
        }
        cr = blockReduceSum(cr, red);
        if (tid == 0) {
            float invN = 1.0f / (float)N;
            float mp = g_sum[0] * invN, mt = g_sum[1] * invN;
            float varP = g_sumsq[0] - (float)N * mp * mp;
            float varT = g_sumsq[1] - (float)N * mt * mt;
            float cov  = cr - (float)N * mp * mt;
            float sp   = cov * rsqrtf(varP * varT);
            out[0] = (1.0f - sp) + g_bce * invN;
            g_cnt[0] = 0; g_cnt[1] = 0; g_cnt2 = 0;   // reset for graph replay
        }
        // reset tickets for next replay
#pragma unroll
        for (int m = 0; m < 4; m++) {
            int i = tid + m * NTHREADS;
            g_tick[0][i] = 0;
            g_tick[1][i] = 0;
        }
    }
}

extern "C" void kernel_launch(void* const* d_in, const int* in_sizes, int n_in,
                              void* d_out, int out_size) {
    const float* yhat = (const float*)d_in[0];
    const float* ytar = (const float*)d_in[1];
    float* out = (float*)d_out;
    cudaFuncSetAttribute(fusedKernel,
                         cudaFuncAttributeMaxDynamicSharedMemorySize, SMEM_BYTES);
    fusedKernel<<<2 * NCTA_ROW, NTHREADS, SMEM_BYTES>>>(yhat, ytar, out);
}

// round 10
// speedup vs baseline: 1.4215x; 1.4215x over previous
#include <cuda_runtime.h>
#include <math.h>

#define N 4096
#define NTHREADS 1024
#define NCTA_ROW 64
#define SLICE 64
#define NCHUNK 64
#define CHUNK 64

typedef unsigned long long u64;
typedef unsigned int u32;

__device__ u64   g_keys[2][N];
__device__ float g_rank[2][N];
__device__ float g_sum[2], g_sumsq[2], g_bce;
__device__ u32   g_tick[2][N];     // tie tickets (reset by finisher each launch)
__device__ u32   g_cnt[2];
__device__ u32   g_cnt2;

// ---- float -> order-preserving uint (ascending), exact inverse ----
__device__ __forceinline__ u32 encodeVal(float v) {
    u32 b = __float_as_uint(v);
    return (b & 0x80000000u) ? ~b : (b | 0x80000000u);
}
__device__ __forceinline__ float decodeVal(u32 e) {
    return (e & 0x80000000u) ? __uint_as_float(e ^ 0x80000000u)
                             : __uint_as_float(~e);
}

__device__ __forceinline__ uint4 packAtom(float S, float W, float C, int st) {
    uint4 a;
    a.x = __float_as_uint(S); a.y = __float_as_uint(W);
    a.z = __float_as_uint(C); a.w = (u32)st;
    return a;
}

__device__ __forceinline__ float blockReduceSum(float v, float* scratch) {
#pragma unroll
    for (int o = 16; o; o >>= 1) v += __shfl_down_sync(0xffffffffu, v, o);
    int w = threadIdx.x >> 5, l = threadIdx.x & 31;
    __syncthreads();
    if (l == 0) scratch[w] = v;
    __syncthreads();
    if (w == 0) {
        float t = scratch[l];   // exactly 32 warps
#pragma unroll
        for (int o = 16; o; o >>= 1) t += __shfl_down_sync(0xffffffffu, t, o);
        if (l == 0) scratch[0] = t;
    }
    __syncthreads();
    return scratch[0];
}

// ---- SMEM byte offsets (identical to R8 layout) ----
#define SM_KARR   0                     // u64[4096] 32768   | counting: u32 enc[4096]
#define SM_STK    32768                 // uint4[4096] 65536 | counting: sPart u32[1024]
#define SM_DENSE  98304                 // uint4[4096] 65536 | scatter: rLoc f[4096]
#define SM_FSTART 163840                // int[4097]
#define SM_FMEAN  180228                // float[4096]
#define SM_CNT    196612                // int[64]
#define SM_OFF    196868                // int[64]
#define SM_RED    197124                // float[32]
#define SM_WHO    197252                // u32[2]
#define SM_NB     197260                // int
#define SMEM_BYTES 197280

__global__ __launch_bounds__(NTHREADS, 1)
void fusedKernel(const float* __restrict__ yhat,
                 const float* __restrict__ ytar,
                 float* __restrict__ out) {
    extern __shared__ char sm[];
    u64*   kArr   = (u64*)(sm + SM_KARR);
    u32*   encArr = (u32*)(sm + SM_KARR);     // counting overlay
    uint4* stk    = (uint4*)(sm + SM_STK);
    u32*   sPart  = (u32*)(sm + SM_STK);      // counting overlay
    uint4* dense  = (uint4*)(sm + SM_DENSE);
    float* rLoc   = (float*)(sm + SM_DENSE);  // scatter overlay
    int*   fStart = (int*)(sm + SM_FSTART);
    float* fMean  = (float*)(sm + SM_FMEAN);
    int*   cntArr = (int*)(sm + SM_CNT);
    int*   offArr = (int*)(sm + SM_OFF);
    float* red    = (float*)(sm + SM_RED);
    u32*   shWho  = (u32*)(sm + SM_WHO);
    int*   nbPtr  = (int*)(sm + SM_NB);

    const int tid  = threadIdx.x;
    const int lane = tid & 31;
    const int wrp  = tid >> 5;
    const int row  = blockIdx.x >> 6;
    const int ctaSlot = blockIdx.x & (NCTA_ROW - 1);
    const float* src = row ? ytar : yhat;

    // ============ Phase 1: u32 rank-by-counting (all 128 CTAs) ============
    {
        float4 v = ((const float4*)src)[tid];
        uint4 ev;
        ev.x = encodeVal(v.x); ev.y = encodeVal(v.y);
        ev.z = encodeVal(v.z); ev.w = encodeVal(v.w);
        ((uint4*)encArr)[tid] = ev;
    }
    __syncthreads();

    {
        // lane = target, warp = value segment; all lanes read the SAME address
        // each iteration -> broadcast LDS.128, 1 wavefront.
        const int seg = wrp & 15;                  // value segment [seg*256, +256)
        const int g   = wrp >> 4;                  // target group (0 or 1)
        const int ii  = ctaSlot * SLICE + g * 32 + lane;
        const u32 ei  = encArr[ii];
        const uint4* base = (const uint4*)(encArr + seg * 256);  // 64 uint4
        u32 c = 0;
#pragma unroll 8
        for (int t = 0; t < 64; ++t) {
            uint4 a = base[t];
            c += (u32)(a.x > ei) + (u32)(a.y > ei)
               + (u32)(a.z > ei) + (u32)(a.w > ei);
        }
        sPart[wrp * 32 + lane] = c;
    }
    __syncthreads();

    if (tid < SLICE) {
        int g = tid >> 5, ln = tid & 31;
        u32 pos = 0;
#pragma unroll
        for (int s = 0; s < 16; ++s)
            pos += sPart[(g * 16 + s) * 32 + ln];
        // pos = # strictly greater; ties get distinct slots via global ticket
        const int i = ctaSlot * SLICE + tid;
        const u32 en = encArr[i];
        u32 tick = atomicAdd(&g_tick[row][pos], 1u);
        g_keys[row][pos + tick] = ((u64)en << 32) | (u32)i;
    }

    // ============ gate 1: last CTA per row continues; rest exit ============
    __threadfence();
    __syncthreads();
    if (tid == 0) shWho[0] = atomicAdd(&g_cnt[row], 1);
    __syncthreads();
    if (shWho[0] != NCTA_ROW - 1) return;
    __threadfence();   // acquire other CTAs' g_keys writes

    // ============ Phase 2: PAV (1 CTA per row) ============
    {
        const u64* gk = g_keys[row];
#pragma unroll
        for (int m = 0; m < 4; m++) {
            int i = tid + m * NTHREADS;
            kArr[i] = gk[i];
        }
    }
    __syncthreads();

    // per-chunk PAV, all-float block state (exact: |sumW| < 2^24)
    if (tid < NCHUNK) {
        const int base = tid * CHUNK;
        float w  = (float)(N - base);            // w(i) = N - i, running
        float tS = decodeVal((u32)(kArr[base] >> 32));
        float tW = w, tC = 1.f;
        float tNum = tS - tW;
        int   tSt = base, sp = 0;
        for (int i = base + 1; i < base + CHUNK; ++i) {
            w -= 1.f;
            float s = decodeVal((u32)(kArr[i] >> 32));
            float cS = s, cW = w, cC = 1.f, cNum = s - w;
            int   cSt = i;
            while (tNum * cC < cNum * tC) {      // pool
                cS += tS; cW += tW; cC += tC; cSt = tSt;
                cNum = cS - cW;
                if (sp == 0) { tC = 0.f; break; }
                sp--;
                uint4 a = stk[base + sp];
                tS = __uint_as_float(a.x); tW = __uint_as_float(a.y);
                tC = __uint_as_float(a.z); tSt = (int)a.w;
                tNum = tS - tW;
            }
            if (tC > 0.f) { stk[base + sp] = packAtom(tS, tW, tC, tSt); sp++; }
            tS = cS; tW = cW; tC = cC; tSt = cSt; tNum = cNum;
        }
        stk[base + sp] = packAtom(tS, tW, tC, tSt); sp++;
        cntArr[tid] = sp;
    }
    __syncthreads();

    if (tid < NCHUNK) {
        int o = 0;
        for (int j = 0; j < tid; j++) o += cntArr[j];
        offArr[tid] = o;
    }
    __syncthreads();

    if (tid < NCHUNK) {
        int o = offArr[tid], c = cntArr[tid];
        for (int b = 0; b < c; b++) dense[o + b] = stk[tid * CHUNK + b];
    }
    __syncthreads();

    const int natoms = offArr[NCHUNK - 1] + cntArr[NCHUNK - 1];

    // serial merge over dense atoms (prefetched); final stack reuses stk
    if (tid == 0) {
        uint4 a0 = dense[0];
        float tS = __uint_as_float(a0.x), tW = __uint_as_float(a0.y);
        float tC = __uint_as_float(a0.z);
        int   tSt = (int)a0.w;
        float tNum = tS - tW;
        int sp = 0;
        uint4 nxt = dense[(natoms > 1) ? 1 : 0];
        for (int t = 1; t < natoms; ++t) {
            uint4 a = nxt;
            nxt = dense[(t + 1 < natoms) ? (t + 1) : t];   // prefetch
            float cS = __uint_as_float(a.x), cW = __uint_as_float(a.y);
            float cC = __uint_as_float(a.z);
            int   cSt = (int)a.w;
            float cNum = cS - cW;
            while (tNum * cC < cNum * tC) {
                cS += tS; cW += tW; cC += tC; cSt = tSt;
                cNum = cS - cW;
                if (sp == 0) { tC = 0.f; break; }
                sp--;
                uint4 p = stk[sp];
                tS = __uint_as_float(p.x); tW = __uint_as_float(p.y);
                tC = __uint_as_float(p.z); tSt = (int)p.w;
                tNum = tS - tW;
            }
            if (tC > 0.f) { stk[sp] = packAtom(tS, tW, tC, tSt); sp++; }
            tS = cS; tW = cW; tC = cC; tSt = cSt; tNum = cNum;
        }
        stk[sp] = packAtom(tS, tW, tC, tSt); sp++;
        *nbPtr = sp;
    }
    __syncthreads();

    const int nb = *nbPtr;
    for (int b = tid; b < nb; b += NTHREADS) {
        uint4 a = stk[b];
        fStart[b] = (int)a.w;
        fMean[b]  = (__uint_as_float(a.x) - __uint_as_float(a.y))
                    / __uint_as_float(a.z);
    }
    if (tid == 0) fStart[nb] = N;
    __syncthreads();

    // ---- scatter + own-row moments (rLoc overlays dense; fMean untouched) ----
    float sR = 0.f, sR2 = 0.f;
#pragma unroll
    for (int m = 0; m < 4; m++) {
        int i = tid + m * NTHREADS;
        u64 kk = kArr[i];
        float s = decodeVal((u32)(kk >> 32));
        int  id = (int)(kk & 0xFFFFFFFFu);
        int lo = 0, hi = nb - 1;
        while (lo < hi) {
            int mid = (lo + hi + 1) >> 1;
            if (fStart[mid] <= i) lo = mid; else hi = mid - 1;
        }
        float r = s - fMean[lo] - 2048.5f;     // shift is Spearman-invariant
        g_rank[row][id] = r;
        rLoc[id] = r;
        sR  += r;
        sR2 += r * r;
    }
    float S  = blockReduceSum(sR, red);
    float S2 = blockReduceSum(sR2, red);

    float B = 0.f;
    if (row == 1) {
        float4 x4 = ((const float4*)yhat)[tid];
        float4 y4 = ((const float4*)ytar)[tid];
        float sb = 0.f;
        sb += fmaxf(x4.x, 0.f) + log1pf(expf(-fabsf(x4.x))) - x4.x * y4.x;
        sb += fmaxf(x4.y, 0.f) + log1pf(expf(-fabsf(x4.y))) - x4.y * y4.y;
        sb += fmaxf(x4.z, 0.f) + log1pf(expf(-fabsf(x4.z))) - x4.z * y4.z;
        sb += fmaxf(x4.w, 0.f) + log1pf(expf(-fabsf(x4.w))) - x4.w * y4.w;
        B = blockReduceSum(sb, red);
    }
    if (tid == 0) {
        g_sum[row]   = S;
        g_sumsq[row] = S2;
        if (row == 1) g_bce = B;
    }

    // ============ gate 2: second of the two row CTAs finishes ============
    __threadfence();
    __syncthreads();
    if (tid == 0) shWho[1] = atomicAdd(&g_cnt2, 1);
    __syncthreads();
    if (shWho[1] != 1) return;
    __threadfence();   // acquire other row's ranks + partials

    {
        const float* other = g_rank[1 - row];
        float cr = 0.f;
#pragma unroll
        for (int m = 0; m < 4; m++) {
            int i = tid + m * NTHREADS;
            cr += other[i] * rLoc[i];
            g_tick[0][i] = 0;            // reset tickets for next replay
            g_tick[1][i] = 0;
        }
        cr = blockReduceSum(cr, red);
        if (tid == 0) {
            float invN = 1.0f / (float)N;
            float mp = g_sum[0] * invN, mt = g_sum[1] * invN;
            float varP = g_sumsq[0] - (float)N * mp * mp;
            float varT = g_sumsq[1] - (float)N * mt * mt;
            float cov  = cr - (float)N * mp * mt;
            float sp   = cov * rsqrtf(varP * varT);
            out[0] = (1.0f - sp) + g_bce * invN;
            g_cnt[0] = 0; g_cnt[1] = 0; g_cnt2 = 0;   // reset for graph replay
        }
    }
}

extern "C" void kernel_launch(void* const* d_in, const int* in_sizes, int n_in,
                              void* d_out, int out_size) {
    const float* yhat = (const float*)d_in[0];
    const float* ytar = (const float*)d_in[1];
    float* out = (float*)d_out;
    cudaFuncSetAttribute(fusedKernel,
                         cudaFuncAttributeMaxDynamicSharedMemorySize, SMEM_BYTES);
    fusedKernel<<<2 * NCTA_ROW, NTHREADS, SMEM_BYTES>>>(yhat, ytar, out);
}

// round 11
// speedup vs baseline: 1.5129x; 1.0643x over previous
#include <cuda_runtime.h>
#include <math.h>

#define N 4096
#define NTHREADS 1024
#define NCTA_ROW 64
#define SLICE 64
#define NCHUNK 128
#define CHUNK 32

typedef unsigned long long u64;
typedef unsigned int u32;

__device__ u64   g_keys[2][N];
__device__ float g_rank[2][N];
__device__ float g_sum[2], g_sumsq[2], g_bce;
__device__ u32   g_tick[2][N];     // tie tickets (reset by finisher each launch)
__device__ u32   g_cnt[2];
__device__ u32   g_cnt2;

// ---- float -> order-preserving uint (ascending), exact inverse ----
__device__ __forceinline__ u32 encodeVal(float v) {
    u32 b = __float_as_uint(v);
    return (b & 0x80000000u) ? ~b : (b | 0x80000000u);
}
__device__ __forceinline__ float decodeVal(u32 e) {
    return (e & 0x80000000u) ? __uint_as_float(e ^ 0x80000000u)
                             : __uint_as_float(~e);
}

// predicated accumulate, guaranteed 2-instr forms on separate pipes
__device__ __forceinline__ void cmpAccF(float& cf, float a, float vi) {
    asm("{.reg .pred p; setp.gt.f32 p, %1, %2;\n\t"
        "@p add.f32 %0, %0, 0f3F800000;}\n"
        : "+f"(cf) : "f"(a), "f"(vi));
}
__device__ __forceinline__ void cmpAccU(u32& c, u32 a, u32 ei) {
    asm("{.reg .pred p; setp.gt.u32 p, %1, %2;\n\t"
        "@p add.u32 %0, %0, 1;}\n"
        : "+r"(c) : "r"(a), "r"(ei));
}

__device__ __forceinline__ uint4 packAtom(float S, float W, float C, int st) {
    uint4 a;
    a.x = __float_as_uint(S); a.y = __float_as_uint(W);
    a.z = __float_as_uint(C); a.w = (u32)st;
    return a;
}

__device__ __forceinline__ float blockReduceSum(float v, float* scratch) {
#pragma unroll
    for (int o = 16; o; o >>= 1) v += __shfl_down_sync(0xffffffffu, v, o);
    int w = threadIdx.x >> 5, l = threadIdx.x & 31;
    __syncthreads();
    if (l == 0) scratch[w] = v;
    __syncthreads();
    if (w == 0) {
        float t = scratch[l];   // exactly 32 warps
#pragma unroll
        for (int o = 16; o; o >>= 1) t += __shfl_down_sync(0xffffffffu, t, o);
        if (l == 0) scratch[0] = t;
    }
    __syncthreads();
    return scratch[0];
}

// ---- SMEM byte offsets ----
#define SM_KARR   0        // u64[4096] 32768   | counting: fArr f32[4096] (16KB)
#define SM_STK    32768    // uint4[4096] 65536 | counting: encArr u32[4096] @32768, sPart u32[2048] @49152
#define SM_DENSE  98304    // uint4[4096] 65536 | scatter: rLoc f[4096]
#define SM_FSTART 163840   // int[4097] 16388
#define SM_FMEAN  180228   // float[4096] 16384
#define SM_CNT    196612   // int[128] 512
#define SM_OFF    197124   // int[128] 512
#define SM_RED    197636   // float[32] 128
#define SM_WHO    197764   // u32[2]
#define SM_NB     197772   // int
#define SMEM_BYTES 197792

__global__ __launch_bounds__(NTHREADS, 1)
void fusedKernel(const float* __restrict__ yhat,
                 const float* __restrict__ ytar,
                 float* __restrict__ out) {
    extern __shared__ char sm[];
    u64*   kArr   = (u64*)(sm + SM_KARR);
    float* fArr   = (float*)(sm + SM_KARR);     // counting overlay
    uint4* stk    = (uint4*)(sm + SM_STK);
    u32*   encArr = (u32*)(sm + SM_STK);        // counting overlay (16KB)
    u32*   sPart  = (u32*)(sm + SM_STK + 16384);// counting overlay (4KB)
    uint4* dense  = (uint4*)(sm + SM_DENSE);
    float* rLoc   = (float*)(sm + SM_DENSE);    // scatter overlay
    int*   fStart = (int*)(sm + SM_FSTART);
    float* fMean  = (float*)(sm + SM_FMEAN);
    int*   cntArr = (int*)(sm + SM_CNT);
    int*   offArr = (int*)(sm + SM_OFF);
    float* red    = (float*)(sm + SM_RED);
    int*   redI   = (int*)(sm + SM_RED);
    u32*   shWho  = (u32*)(sm + SM_WHO);
    int*   nbPtr  = (int*)(sm + SM_NB);

    const int tid  = threadIdx.x;
    const int lane = tid & 31;
    const int wrp  = tid >> 5;
    const int row  = blockIdx.x >> 6;
    const int ctaSlot = blockIdx.x & (NCTA_ROW - 1);
    const float* src = row ? ytar : yhat;

    // ============ Phase 1: dual-pipe rank-by-counting (128 CTAs) ============
    {
        float4 v = ((const float4*)src)[tid];
        ((float4*)fArr)[tid] = v;
        uint4 ev;
        ev.x = encodeVal(v.x); ev.y = encodeVal(v.y);
        ev.z = encodeVal(v.z); ev.w = encodeVal(v.w);
        ((uint4*)encArr)[tid] = ev;
    }
    __syncthreads();

    {
        // lane = target, warp = value segment (256 values). First 128 values
        // compared as float (fma pipe), last 128 as encoded u32 (alu pipe).
        const int seg = wrp & 15;
        const int g   = wrp >> 4;
        const int ii  = ctaSlot * SLICE + g * 32 + lane;
        const float vi = fArr[ii];
        const u32   ei = encArr[ii];
        const float4* fq = (const float4*)(fArr + seg * 256);     // quads 0..63
        const uint4*  uq = (const uint4*)(encArr + seg * 256);
        float cf = 0.f;
        u32   ci = 0;
#pragma unroll 4
        for (int t = 0; t < 32; ++t) {
            float4 f = fq[t];           // values [seg*256, +128)
            uint4  u = uq[t + 32];      // values [seg*256+128, +128)
            cmpAccF(cf, f.x, vi); cmpAccU(ci, u.x, ei);
            cmpAccF(cf, f.y, vi); cmpAccU(ci, u.y, ei);
            cmpAccF(cf, f.z, vi); cmpAccU(ci, u.z, ei);
            cmpAccF(cf, f.w, vi); cmpAccU(ci, u.w, ei);
        }
        sPart[wrp * 32 + lane] = ci + (u32)cf;
    }
    __syncthreads();

    if (tid < SLICE) {
        int g = tid >> 5, ln = tid & 31;
        u32 pos = 0;
#pragma unroll
        for (int s = 0; s < 16; ++s)
            pos += sPart[(g * 16 + s) * 32 + ln];
        // pos = # strictly greater; ties get distinct slots via global ticket
        const int i = ctaSlot * SLICE + tid;
        const u32 en = encArr[i];
        u32 tick = atomicAdd(&g_tick[row][pos], 1u);
        g_keys[row][pos + tick] = ((u64)en << 32) | (u32)i;
    }

    // ============ gate 1: last CTA per row continues; rest exit ============
    __threadfence();
    __syncthreads();
    if (tid == 0) shWho[0] = atomicAdd(&g_cnt[row], 1);
    __syncthreads();
    if (shWho[0] != NCTA_ROW - 1) return;
    __threadfence();   // acquire other CTAs' g_keys writes

    // ============ Phase 2: PAV (1 CTA per row) ============
    {
        const u64* gk = g_keys[row];
#pragma unroll
        for (int m = 0; m < 4; m++) {
            int i = tid + m * NTHREADS;
            kArr[i] = gk[i];
        }
    }
    __syncthreads();

    // per-chunk PAV, all-float block state (exact: |sumW| < 2^24)
    if (tid < NCHUNK) {
        const int base = tid * CHUNK;
        float w  = (float)(N - base);            // w(i) = N - i, running
        float tS = decodeVal((u32)(kArr[base] >> 32));
        float tW = w, tC = 1.f;
        float tNum = tS - tW;
        int   tSt = base, sp = 0;
        for (int i = base + 1; i < base + CHUNK; ++i) {
            w -= 1.f;
            float s = decodeVal((u32)(kArr[i] >> 32));
            float cS = s, cW = w, cC = 1.f, cNum = s - w;
            int   cSt = i;
            while (tNum * cC < cNum * tC) {      // pool
                cS += tS; cW += tW; cC += tC; cSt = tSt;
                cNum = cS - cW;
                if (sp == 0) { tC = 0.f; break; }
                sp--;
                uint4 a = stk[base + sp];
                tS = __uint_as_float(a.x); tW = __uint_as_float(a.y);
                tC = __uint_as_float(a.z); tSt = (int)a.w;
                tNum = tS - tW;
            }
            if (tC > 0.f) { stk[base + sp] = packAtom(tS, tW, tC, tSt); sp++; }
            tS = cS; tW = cW; tC = cC; tSt = cSt; tNum = cNum;
        }
        stk[base + sp] = packAtom(tS, tW, tC, tSt); sp++;
        cntArr[tid] = sp;
    }
    __syncthreads();

    // exclusive scan of 128 chunk counts (4 warps, shuffle scan)
    int myCnt = 0, incl = 0;
    if (tid < NCHUNK) {
        myCnt = cntArr[tid];
        incl = myCnt;
#pragma unroll
        for (int o = 1; o < 32; o <<= 1) {
            int y = __shfl_up_sync(0xffffffffu, incl, o);
            if (lane >= o) incl += y;
        }
        if (lane == 31) redI[wrp] = incl;
    }
    __syncthreads();
    if (tid < NCHUNK) {
        int wb = 0;
#pragma unroll
        for (int j = 0; j < 3; ++j)
            if (j < wrp) wb += redI[j];
        offArr[tid] = wb + incl - myCnt;
    }
    __syncthreads();

    if (tid < NCHUNK) {
        int o = offArr[tid];
        for (int b = 0; b < myCnt; b++) dense[o + b] = stk[tid * CHUNK + b];
    }
    __syncthreads();

    const int natoms = offArr[NCHUNK - 1] + cntArr[NCHUNK - 1];

    // serial merge over dense atoms (prefetched); final stack reuses stk
    if (tid == 0) {
        uint4 a0 = dense[0];
        float tS = __uint_as_float(a0.x), tW = __uint_as_float(a0.y);
        float tC = __uint_as_float(a0.z);
        int   tSt = (int)a0.w;
        float tNum = tS - tW;
        int sp = 0;
        uint4 nxt = dense[(natoms > 1) ? 1 : 0];
        for (int t = 1; t < natoms; ++t) {
            uint4 a = nxt;
            nxt = dense[(t + 1 < natoms) ? (t + 1) : t];   // prefetch
            float cS = __uint_as_float(a.x), cW = __uint_as_float(a.y);
            float cC = __uint_as_float(a.z);
            int   cSt = (int)a.w;
            float cNum = cS - cW;
            while (tNum * cC < cNum * tC) {
                cS += tS; cW += tW; cC += tC; cSt = tSt;
                cNum = cS - cW;
                if (sp == 0) { tC = 0.f; break; }
                sp--;
                uint4 p = stk[sp];
                tS = __uint_as_float(p.x); tW = __uint_as_float(p.y);
                tC = __uint_as_float(p.z); tSt = (int)p.w;
                tNum = tS - tW;
            }
            if (tC > 0.f) { stk[sp] = packAtom(tS, tW, tC, tSt); sp++; }
            tS = cS; tW = cW; tC = cC; tSt = cSt; tNum = cNum;
        }
        stk[sp] = packAtom(tS, tW, tC, tSt); sp++;
        *nbPtr = sp;
    }
    __syncthreads();

    const int nb = *nbPtr;
    for (int b = tid; b < nb; b += NTHREADS) {
        uint4 a = stk[b];
        fStart[b] = (int)a.w;
        fMean[b]  = (__uint_as_float(a.x) - __uint_as_float(a.y))
                    / __uint_as_float(a.z);
    }
    if (tid == 0) fStart[nb] = N;
    __syncthreads();

    // ---- scatter + own-row moments (rLoc overlays dense; fMean untouched) ----
    float sR = 0.f, sR2 = 0.f;
#pragma unroll
    for (int m = 0; m < 4; m++) {
        int i = tid + m * NTHREADS;
        u64 kk = kArr[i];
        float s = decodeVal((u32)(kk >> 32));
        int  id = (int)(kk & 0xFFFFFFFFu);
        int lo = 0, hi = nb - 1;
        while (lo < hi) {
            int mid = (lo + hi + 1) >> 1;
            if (fStart[mid] <= i) lo = mid; else hi = mid - 1;
        }
        float r = s - fMean[lo] - 2048.5f;     // shift is Spearman-invariant
        g_rank[row][id] = r;
        rLoc[id] = r;
        sR  += r;
        sR2 += r * r;
    }
    float S  = blockReduceSum(sR, red);
    float S2 = blockReduceSum(sR2, red);

    float B = 0.f;
    if (row == 1) {
        float4 x4 = ((const float4*)yhat)[tid];
        float4 y4 = ((const float4*)ytar)[tid];
        float sb = 0.f;
        sb += fmaxf(x4.x, 0.f) + log1pf(expf(-fabsf(x4.x))) - x4.x * y4.x;
        sb += fmaxf(x4.y, 0.f) + log1pf(expf(-fabsf(x4.y))) - x4.y * y4.y;
        sb += fmaxf(x4.z, 0.f) + log1pf(expf(-fabsf(x4.z))) - x4.z * y4.z;
        sb += fmaxf(x4.w, 0.f) + log1pf(expf(-fabsf(x4.w))) - x4.w * y4.w;
        B = blockReduceSum(sb, red);
    }
    if (tid == 0) {
        g_sum[row]   = S;
        g_sumsq[row] = S2;
        if (row == 1) g_bce = B;
    }

    // ============ gate 2: second of the two row CTAs finishes ============
    __threadfence();
    __syncthreads();
    if (tid == 0) shWho[1] = atomicAdd(&g_cnt2, 1);
    __syncthreads();
    if (shWho[1] != 1) return;
    __threadfence();   // acquire other row's ranks + partials

    {
        const float* other = g_rank[1 - row];
        float cr = 0.f;
#pragma unroll
        for (int m = 0; m < 4; m++) {
            int i = tid + m * NTHREADS;
            cr += other[i] * rLoc[i];
            g_tick[0][i] = 0;            // reset tickets for next replay
            g_tick[1][i] = 0;
        }
        cr = blockReduceSum(cr, red);
        if (tid == 0) {
            float invN = 1.0f / (float)N;
            float mp = g_sum[0] * invN, mt = g_sum[1] * invN;
            float varP = g_sumsq[0] - (float)N * mp * mp;
            float varT = g_sumsq[1] - (float)N * mt * mt;
            float cov  = cr - (float)N * mp * mt;
            float sp   = cov * rsqrtf(varP * varT);
            out[0] = (1.0f - sp) + g_bce * invN;
            g_cnt[0] = 0; g_cnt[1] = 0; g_cnt2 = 0;   // reset for graph replay
        }
    }
}

extern "C" void kernel_launch(void* const* d_in, const int* in_sizes, int n_in,
                              void* d_out, int out_size) {
    const float* yhat = (const float*)d_in[0];
    const float* ytar = (const float*)d_in[1];
    float* out = (float*)d_out;
    cudaFuncSetAttribute(fusedKernel,
                         cudaFuncAttributeMaxDynamicSharedMemorySize, SMEM_BYTES);
    fusedKernel<<<2 * NCTA_ROW, NTHREADS, SMEM_BYTES>>>(yhat, ytar, out);
}

// round 12
// speedup vs baseline: 1.6434x; 1.0863x over previous
#include <cuda_runtime.h>
#include <math.h>

#define N 4096
#define NTHREADS 1024
#define NCTA_ROW 64
#define SLICE 64
#define NCHUNK 128
#define CHUNK 32

typedef unsigned long long u64;
typedef unsigned int u32;

__device__ u64   g_keys[2][N];
__device__ float g_rank[2][N];
__device__ float g_sum[2], g_sumsq[2], g_bce;
__device__ u32   g_tick[2][N];     // tie tickets (reset by finisher each launch)
__device__ u32   g_cnt[2];
__device__ u32   g_cnt2;

// ---- float -> order-preserving uint (ascending), exact inverse ----
__device__ __forceinline__ u32 encodeVal(float v) {
    u32 b = __float_as_uint(v);
    return (b & 0x80000000u) ? ~b : (b | 0x80000000u);
}
__device__ __forceinline__ float decodeVal(u32 e) {
    return (e & 0x80000000u) ? __uint_as_float(e ^ 0x80000000u)
                             : __uint_as_float(~e);
}

// predicated accumulate, guaranteed 2-instr forms on separate pipes
__device__ __forceinline__ void cmpAccF(float& cf, float a, float vi) {
    asm("{.reg .pred p; setp.gt.f32 p, %1, %2;\n\t"
        "@p add.f32 %0, %0, 0f3F800000;}\n"
        : "+f"(cf) : "f"(a), "f"(vi));
}
__device__ __forceinline__ void cmpAccU(u32& c, u32 a, u32 ei) {
    asm("{.reg .pred p; setp.gt.u32 p, %1, %2;\n\t"
        "@p add.u32 %0, %0, 1;}\n"
        : "+r"(c) : "r"(a), "r"(ei));
}

__device__ __forceinline__ uint4 packAtom(float S, float W, float C, int st) {
    uint4 a;
    a.x = __float_as_uint(S); a.y = __float_as_uint(W);
    a.z = __float_as_uint(C); a.w = (u32)st;
    return a;
}

__device__ __forceinline__ float blockReduceSum(float v, float* scratch) {
#pragma unroll
    for (int o = 16; o; o >>= 1) v += __shfl_down_sync(0xffffffffu, v, o);
    int w = threadIdx.x >> 5, l = threadIdx.x & 31;
    __syncthreads();
    if (l == 0) scratch[w] = v;
    __syncthreads();
    if (w == 0) {
        float t = scratch[l];   // exactly 32 warps
#pragma unroll
        for (int o = 16; o; o >>= 1) t += __shfl_down_sync(0xffffffffu, t, o);
        if (l == 0) scratch[0] = t;
    }
    __syncthreads();
    return scratch[0];
}

// ---- SMEM byte offsets ----
#define SM_KARR   0        // u64[4096] 32768   | counting: fArr f32[4096] (16KB)
#define SM_STK    32768    // uint4[4096] 65536 | counting: encArr u32[4096] @32768, sPart u32[2048] @49152
#define SM_DENSE  98304    // uint4[4096] 65536 | scatter: rLoc f[4096]
#define SM_FSTART 163840   // int[4097] 16388
#define SM_FMEAN  180228   // float[4096] 16384
#define SM_CNT    196612   // int[128] 512
#define SM_OFF    197124   // int[128] 512
#define SM_RED    197636   // float[32] 128
#define SM_WHO    197764   // u32[2]
#define SM_NB     197772   // int
#define SMEM_BYTES 197792

__global__ __launch_bounds__(NTHREADS, 1)
void fusedKernel(const float* __restrict__ yhat,
                 const float* __restrict__ ytar,
                 float* __restrict__ out) {
    extern __shared__ char sm[];
    u64*   kArr   = (u64*)(sm + SM_KARR);
    float* fArr   = (float*)(sm + SM_KARR);     // counting overlay
    uint4* stk    = (uint4*)(sm + SM_STK);
    u32*   encArr = (u32*)(sm + SM_STK);        // counting overlay (16KB)
    u32*   sPart  = (u32*)(sm + SM_STK + 16384);// counting overlay (4KB)
    uint4* dense  = (uint4*)(sm + SM_DENSE);
    float* rLoc   = (float*)(sm + SM_DENSE);    // scatter overlay (after extract)
    int*   fStart = (int*)(sm + SM_FSTART);
    float* fMean  = (float*)(sm + SM_FMEAN);
    int*   cntA   = (int*)(sm + SM_CNT);
    int*   cntB   = (int*)(sm + SM_OFF);
    float* red    = (float*)(sm + SM_RED);
    u32*   shWho  = (u32*)(sm + SM_WHO);
    int*   nbPtr  = (int*)(sm + SM_NB);

    const int tid  = threadIdx.x;
    const int lane = tid & 31;
    const int wrp  = tid >> 5;
    const int row  = blockIdx.x >> 6;
    const int ctaSlot = blockIdx.x & (NCTA_ROW - 1);
    const float* src = row ? ytar : yhat;

    // ============ Phase 1: dual-pipe rank-by-counting (128 CTAs) ============
    {
        float4 v = ((const float4*)src)[tid];
        ((float4*)fArr)[tid] = v;
        uint4 ev;
        ev.x = encodeVal(v.x); ev.y = encodeVal(v.y);
        ev.z = encodeVal(v.z); ev.w = encodeVal(v.w);
        ((uint4*)encArr)[tid] = ev;
    }
    __syncthreads();

    {
        // lane = target, warp = value segment (256 values). First 128 values
        // compared as float (fma pipe), last 128 as encoded u32 (alu pipe).
        const int seg = wrp & 15;
        const int g   = wrp >> 4;
        const int ii  = ctaSlot * SLICE + g * 32 + lane;
        const float vi = fArr[ii];
        const u32   ei = encArr[ii];
        const float4* fq = (const float4*)(fArr + seg * 256);
        const uint4*  uq = (const uint4*)(encArr + seg * 256);
        float cf = 0.f;
        u32   ci = 0;
#pragma unroll 8
        for (int t = 0; t < 32; ++t) {
            float4 f = fq[t];           // values [seg*256, +128)
            uint4  u = uq[t + 32];      // values [seg*256+128, +128)
            cmpAccF(cf, f.x, vi); cmpAccU(ci, u.x, ei);
            cmpAccF(cf, f.y, vi); cmpAccU(ci, u.y, ei);
            cmpAccF(cf, f.z, vi); cmpAccU(ci, u.z, ei);
            cmpAccF(cf, f.w, vi); cmpAccU(ci, u.w, ei);
        }
        sPart[wrp * 32 + lane] = ci + (u32)cf;
    }
    __syncthreads();

    if (tid < SLICE) {
        int g = tid >> 5, ln = tid & 31;
        u32 pos = 0;
#pragma unroll
        for (int s = 0; s < 16; ++s)
            pos += sPart[(g * 16 + s) * 32 + ln];
        // pos = # strictly greater; ties get distinct slots via global ticket
        const int i = ctaSlot * SLICE + tid;
        const u32 en = encArr[i];
        u32 tick = atomicAdd(&g_tick[row][pos], 1u);
        g_keys[row][pos + tick] = ((u64)en << 32) | (u32)i;
    }

    // ============ gate 1: last CTA per row continues; rest exit ============
    __threadfence();
    __syncthreads();
    if (tid == 0) shWho[0] = atomicAdd(&g_cnt[row], 1);
    __syncthreads();
    if (shWho[0] != NCTA_ROW - 1) return;
    __threadfence();   // acquire other CTAs' g_keys writes

    // ============ Phase 2: PAV (1 CTA per row) ============
    {
        const u64* gk = g_keys[row];
#pragma unroll
        for (int m = 0; m < 4; m++) {
            int i = tid + m * NTHREADS;
            kArr[i] = gk[i];
        }
    }
    __syncthreads();

    // per-chunk PAV, all-float block state (exact: |sumW| < 2^24)
    if (tid < NCHUNK) {
        const int base = tid * CHUNK;
        float w  = (float)(N - base);            // w(i) = N - i, running
        float tS = decodeVal((u32)(kArr[base] >> 32));
        float tW = w, tC = 1.f;
        float tNum = tS - tW;
        int   tSt = base, sp = 0;
        for (int i = base + 1; i < base + CHUNK; ++i) {
            w -= 1.f;
            float s = decodeVal((u32)(kArr[i] >> 32));
            float cS = s, cW = w, cC = 1.f, cNum = s - w;
            int   cSt = i;
            while (tNum * cC < cNum * tC) {      // pool
                cS += tS; cW += tW; cC += tC; cSt = tSt;
                cNum = cS - cW;
                if (sp == 0) { tC = 0.f; break; }
                sp--;
                uint4 a = stk[base + sp];
                tS = __uint_as_float(a.x); tW = __uint_as_float(a.y);
                tC = __uint_as_float(a.z); tSt = (int)a.w;
                tNum = tS - tW;
            }
            if (tC > 0.f) { stk[base + sp] = packAtom(tS, tW, tC, tSt); sp++; }
            tS = cS; tW = cW; tC = cC; tSt = cSt; tNum = cNum;
        }
        stk[base + sp] = packAtom(tS, tW, tC, tSt); sp++;
        cntA[tid] = sp;
    }

    // ---- tree merge: 7 levels of parallel pairwise PAV-list merges ----
    // Merging left+right lists: left's block means strictly decrease, so
    // replaying left onto an empty stack never pools; streaming right's atoms
    // pools exactly as the serial left-to-right stream would. Hierarchical
    // merge therefore yields the identical final block list.
    {
        uint4* srcB = stk;   uint4* dstB = dense;
        int*   sCnt = cntA;  int*   dCnt = cntB;
        int NL = NCHUNK, S = CHUNK;
        while (NL > 1) {
            __syncthreads();
            if (tid < (NL >> 1)) {
                const uint4* L = srcB + (2 * tid) * S;
                const uint4* R = srcB + (2 * tid + 1) * S;
                uint4* D = dstB + tid * (2 * S);
                int la = sCnt[2 * tid], lb = sCnt[2 * tid + 1];
                // copy left list except its last block (held in registers)
                for (int j = 0; j < la - 1; j++) D[j] = L[j];
                uint4 a = L[la - 1];
                float tS = __uint_as_float(a.x), tW = __uint_as_float(a.y);
                float tC = __uint_as_float(a.z);
                int   tSt = (int)a.w;
                float tNum = tS - tW;
                int sp = la - 1;
                for (int r = 0; r < lb; r++) {
                    uint4 b = R[r];
                    float cS = __uint_as_float(b.x), cW = __uint_as_float(b.y);
                    float cC = __uint_as_float(b.z);
                    int   cSt = (int)b.w;
                    float cNum = cS - cW;
                    while (tNum * cC < cNum * tC) {
                        cS += tS; cW += tW; cC += tC; cSt = tSt;
                        cNum = cS - cW;
                        if (sp == 0) { tC = 0.f; break; }
                        sp--;
                        uint4 p = D[sp];
                        tS = __uint_as_float(p.x); tW = __uint_as_float(p.y);
                        tC = __uint_as_float(p.z); tSt = (int)p.w;
                        tNum = tS - tW;
                    }
                    if (tC > 0.f) { D[sp++] = packAtom(tS, tW, tC, tSt); }
                    tS = cS; tW = cW; tC = cC; tSt = cSt; tNum = cNum;
                }
                D[sp++] = packAtom(tS, tW, tC, tSt);
                dCnt[tid] = sp;
            }
            uint4* tb = srcB; srcB = dstB; dstB = tb;
            int*   tc = sCnt; sCnt = dCnt; dCnt = tc;
            NL >>= 1; S <<= 1;
        }
        __syncthreads();
        // final list is in srcB (== dense after 7 levels), length sCnt[0]
        if (tid == 0) *nbPtr = sCnt[0];
    }
    __syncthreads();

    const int nb = *nbPtr;
    for (int b = tid; b < nb; b += NTHREADS) {
        uint4 a = dense[b];
        fStart[b] = (int)a.w;
        fMean[b]  = (__uint_as_float(a.x) - __uint_as_float(a.y))
                    / __uint_as_float(a.z);
    }
    if (tid == 0) fStart[nb] = N;
    __syncthreads();

    // ---- scatter + own-row moments (rLoc overlays dense; extract done) ----
    float sR = 0.f, sR2 = 0.f;
#pragma unroll
    for (int m = 0; m < 4; m++) {
        int i = tid + m * NTHREADS;
        u64 kk = kArr[i];
        float s = decodeVal((u32)(kk >> 32));
        int  id = (int)(kk & 0xFFFFFFFFu);
        int lo = 0, hi = nb - 1;
        while (lo < hi) {
            int mid = (lo + hi + 1) >> 1;
            if (fStart[mid] <= i) lo = mid; else hi = mid - 1;
        }
        float r = s - fMean[lo] - 2048.5f;     // shift is Spearman-invariant
        g_rank[row][id] = r;
        rLoc[id] = r;
        sR  += r;
        sR2 += r * r;
    }
    float S  = blockReduceSum(sR, red);
    float S2 = blockReduceSum(sR2, red);

    float B = 0.f;
    if (row == 1) {
        float4 x4 = ((const float4*)yhat)[tid];
        float4 y4 = ((const float4*)ytar)[tid];
        float sb = 0.f;
        sb += fmaxf(x4.x, 0.f) + log1pf(expf(-fabsf(x4.x))) - x4.x * y4.x;
        sb += fmaxf(x4.y, 0.f) + log1pf(expf(-fabsf(x4.y))) - x4.y * y4.y;
        sb += fmaxf(x4.z, 0.f) + log1pf(expf(-fabsf(x4.z))) - x4.z * y4.z;
        sb += fmaxf(x4.w, 0.f) + log1pf(expf(-fabsf(x4.w))) - x4.w * y4.w;
        B = blockReduceSum(sb, red);
    }
    if (tid == 0) {
        g_sum[row]   = S;
        g_sumsq[row] = S2;
        if (row == 1) g_bce = B;
    }

    // ============ gate 2: second of the two row CTAs finishes ============
    __threadfence();
    __syncthreads();
    if (tid == 0) shWho[1] = atomicAdd(&g_cnt2, 1);
    __syncthreads();
    if (shWho[1] != 1) return;
    __threadfence();   // acquire other row's ranks + partials

    {
        const float* other = g_rank[1 - row];
        float cr = 0.f;
#pragma unroll
        for (int m = 0; m < 4; m++) {
            int i = tid + m * NTHREADS;
            cr += other[i] * rLoc[i];
            g_tick[0][i] = 0;            // reset tickets for next replay
            g_tick[1][i] = 0;
        }
        cr = blockReduceSum(cr, red);
        if (tid == 0) {
            float invN = 1.0f / (float)N;
            float mp = g_sum[0] * invN, mt = g_sum[1] * invN;
            float varP = g_sumsq[0] - (float)N * mp * mp;
            float varT = g_sumsq[1] - (float)N * mt * mt;
            float cov  = cr - (float)N * mp * mt;
            float sp   = cov * rsqrtf(varP * varT);
            out[0] = (1.0f - sp) + g_bce * invN;
            g_cnt[0] = 0; g_cnt[1] = 0; g_cnt2 = 0;   // reset for graph replay
        }
    }
}

extern "C" void kernel_launch(void* const* d_in, const int* in_sizes, int n_in,
                              void* d_out, int out_size) {
    const float* yhat = (const float*)d_in[0];
    const float* ytar = (const float*)d_in[1];
    float* out = (float*)d_out;
    cudaFuncSetAttribute(fusedKernel,
                         cudaFuncAttributeMaxDynamicSharedMemorySize, SMEM_BYTES);
    fusedKernel<<<2 * NCTA_ROW, NTHREADS, SMEM_BYTES>>>(yhat, ytar, out);
}

// round 13
// speedup vs baseline: 1.8343x; 1.1161x over previous
#include <cuda_runtime.h>
#include <math.h>

#define N 4096
#define NTHREADS 1024
#define NCTA_ROW 64
#define SLICE 64
#define NCHUNK 256
#define CHUNK 16

typedef unsigned long long u64;
typedef unsigned int u32;

__device__ u64   g_keys[2][N];
__device__ float g_rank[2][N];
__device__ float g_sum[2], g_sumsq[2], g_bce;
__device__ u32   g_tick[2][N];     // tie tickets (reset by finisher each launch)
__device__ u32   g_cnt[2];
__device__ u32   g_cnt2;

// ---- float -> order-preserving uint (ascending), exact inverse ----
__device__ __forceinline__ u32 encodeVal(float v) {
    u32 b = __float_as_uint(v);
    return (b & 0x80000000u) ? ~b : (b | 0x80000000u);
}
__device__ __forceinline__ float decodeVal(u32 e) {
    return (e & 0x80000000u) ? __uint_as_float(e ^ 0x80000000u)
                             : __uint_as_float(~e);
}

// predicated accumulate, guaranteed 2-instr forms on separate pipes
__device__ __forceinline__ void cmpAccF(float& cf, float a, float vi) {
    asm("{.reg .pred p; setp.gt.f32 p, %1, %2;\n\t"
        "@p add.f32 %0, %0, 0f3F800000;}\n"
        : "+f"(cf) : "f"(a), "f"(vi));
}
__device__ __forceinline__ void cmpAccU(u32& c, u32 a, u32 ei) {
    asm("{.reg .pred p; setp.gt.u32 p, %1, %2;\n\t"
        "@p add.u32 %0, %0, 1;}\n"
        : "+r"(c) : "r"(a), "r"(ei));
}

__device__ __forceinline__ uint4 packAtom(float S, float W, float C, int st) {
    uint4 a;
    a.x = __float_as_uint(S); a.y = __float_as_uint(W);
    a.z = __float_as_uint(C); a.w = (u32)st;
    return a;
}

__device__ __forceinline__ float blockReduceSum(float v, float* scratch) {
#pragma unroll
    for (int o = 16; o; o >>= 1) v += __shfl_down_sync(0xffffffffu, v, o);
    int w = threadIdx.x >> 5, l = threadIdx.x & 31;
    __syncthreads();
    if (l == 0) scratch[w] = v;
    __syncthreads();
    if (w == 0) {
        float t = scratch[l];   // exactly 32 warps
#pragma unroll
        for (int o = 16; o; o >>= 1) t += __shfl_down_sync(0xffffffffu, t, o);
        if (l == 0) scratch[0] = t;
    }
    __syncthreads();
    return scratch[0];
}

// fused 3-way block reduction: one scratch round instead of three
__device__ __forceinline__ void blockReduce3(float& a, float& b, float& c,
                                             float* scratch) {
#pragma unroll
    for (int o = 16; o; o >>= 1) {
        a += __shfl_down_sync(0xffffffffu, a, o);
        b += __shfl_down_sync(0xffffffffu, b, o);
        c += __shfl_down_sync(0xffffffffu, c, o);
    }
    int w = threadIdx.x >> 5, l = threadIdx.x & 31;
    __syncthreads();
    if (l == 0) { scratch[w] = a; scratch[32 + w] = b; scratch[64 + w] = c; }
    __syncthreads();
    if (w == 0) {
        float ta = scratch[l], tb = scratch[32 + l], tc = scratch[64 + l];
#pragma unroll
        for (int o = 16; o; o >>= 1) {
            ta += __shfl_down_sync(0xffffffffu, ta, o);
            tb += __shfl_down_sync(0xffffffffu, tb, o);
            tc += __shfl_down_sync(0xffffffffu, tc, o);
        }
        if (l == 0) { scratch[0] = ta; scratch[32] = tb; scratch[64] = tc; }
    }
    __syncthreads();
    a = scratch[0]; b = scratch[32]; c = scratch[64];
}

// ---- SMEM byte offsets ----
#define SM_KARR   0        // u64[4096] 32768   | counting: fArr f32[4096] (16KB)
#define SM_STK    32768    // uint4[4096] 65536 | counting: encArr u32[4096] @32768, sPart u32[1024] @49152
#define SM_DENSE  98304    // uint4[4096] 65536 | scatter: rLoc f[4096]
#define SM_FSTART 163840   // int[4097] 16388
#define SM_FMEAN  180228   // float[4096] 16384
#define SM_CNTA   196612   // int[256] 1024
#define SM_CNTB   197636   // int[256] 1024
#define SM_RED    198660   // float[96] 384
#define SM_WHO    199044   // u32[2]
#define SM_NB     199052   // int
#define SMEM_BYTES 199072

__global__ __launch_bounds__(NTHREADS, 1)
void fusedKernel(const float* __restrict__ yhat,
                 const float* __restrict__ ytar,
                 float* __restrict__ out) {
    extern __shared__ char sm[];
    u64*   kArr   = (u64*)(sm + SM_KARR);
    float* fArr   = (float*)(sm + SM_KARR);     // counting overlay
    uint4* stk    = (uint4*)(sm + SM_STK);
    u32*   encArr = (u32*)(sm + SM_STK);        // counting overlay (16KB)
    u32*   sPart  = (u32*)(sm + SM_STK + 16384);// counting overlay (4KB)
    uint4* dense  = (uint4*)(sm + SM_DENSE);
    float* rLoc   = (float*)(sm + SM_DENSE);    // scatter overlay (after extract)
    int*   fStart = (int*)(sm + SM_FSTART);
    float* fMean  = (float*)(sm + SM_FMEAN);
    int*   cntA   = (int*)(sm + SM_CNTA);
    int*   cntB   = (int*)(sm + SM_CNTB);
    float* red    = (float*)(sm + SM_RED);
    u32*   shWho  = (u32*)(sm + SM_WHO);
    int*   nbPtr  = (int*)(sm + SM_NB);

    const int tid  = threadIdx.x;
    const int lane = tid & 31;
    const int wrp  = tid >> 5;
    const int row  = blockIdx.x >> 6;
    const int ctaSlot = blockIdx.x & (NCTA_ROW - 1);
    const float* src = row ? ytar : yhat;

    // ============ Phase 1: dual-pipe rank-by-counting (128 CTAs) ============
    {
        float4 v = ((const float4*)src)[tid];
        ((float4*)fArr)[tid] = v;
        uint4 ev;
        ev.x = encodeVal(v.x); ev.y = encodeVal(v.y);
        ev.z = encodeVal(v.z); ev.w = encodeVal(v.w);
        ((uint4*)encArr)[tid] = ev;
    }
    __syncthreads();

    {
        // lane = target, warp = value segment (256 values). First 128 values
        // compared as float (fma pipe), last 128 as encoded u32 (alu pipe).
        const int seg = wrp & 15;
        const int g   = wrp >> 4;
        const int ii  = ctaSlot * SLICE + g * 32 + lane;
        const float vi = fArr[ii];
        const u32   ei = encArr[ii];
        const float4* fq = (const float4*)(fArr + seg * 256);
        const uint4*  uq = (const uint4*)(encArr + seg * 256);
        float cf = 0.f;
        u32   ci = 0;
#pragma unroll 16
        for (int t = 0; t < 32; ++t) {
            float4 f = fq[t];           // values [seg*256, +128)
            uint4  u = uq[t + 32];      // values [seg*256+128, +128)
            cmpAccF(cf, f.x, vi); cmpAccU(ci, u.x, ei);
            cmpAccF(cf, f.y, vi); cmpAccU(ci, u.y, ei);
            cmpAccF(cf, f.z, vi); cmpAccU(ci, u.z, ei);
            cmpAccF(cf, f.w, vi); cmpAccU(ci, u.w, ei);
        }
        sPart[wrp * 32 + lane] = ci + (u32)cf;
    }
    __syncthreads();

    if (tid < SLICE) {
        int g = tid >> 5, ln = tid & 31;
        u32 pos = 0;
#pragma unroll
        for (int s = 0; s < 16; ++s)
            pos += sPart[(g * 16 + s) * 32 + ln];
        // pos = # strictly greater; ties get distinct slots via global ticket
        const int i = ctaSlot * SLICE + tid;
        const u32 en = encArr[i];
        u32 tick = atomicAdd(&g_tick[row][pos], 1u);
        g_keys[row][pos + tick] = ((u64)en << 32) | (u32)i;
    }

    // ============ gate 1: last CTA per row continues; rest exit ============
    __threadfence();
    __syncthreads();
    if (tid == 0) shWho[0] = atomicAdd(&g_cnt[row], 1);
    __syncthreads();
    if (shWho[0] != NCTA_ROW - 1) return;
    __threadfence();   // acquire other CTAs' g_keys writes

    // ============ Phase 2: PAV (1 CTA per row) ============
    {
        const u64* gk = g_keys[row];
#pragma unroll
        for (int m = 0; m < 4; m++) {
            int i = tid + m * NTHREADS;
            kArr[i] = gk[i];
        }
    }
    __syncthreads();

    // per-chunk PAV, all-float block state (exact: |sumW| < 2^24)
    if (tid < NCHUNK) {
        const int base = tid * CHUNK;
        float w  = (float)(N - base);            // w(i) = N - i, running
        float tS = decodeVal((u32)(kArr[base] >> 32));
        float tW = w, tC = 1.f;
        float tNum = tS - tW;
        int   tSt = base, sp = 0;
        for (int i = base + 1; i < base + CHUNK; ++i) {
            w -= 1.f;
            float s = decodeVal((u32)(kArr[i] >> 32));
            float cS = s, cW = w, cC = 1.f, cNum = s - w;
            int   cSt = i;
            while (tNum * cC < cNum * tC) {      // pool
                cS += tS; cW += tW; cC += tC; cSt = tSt;
                cNum = cS - cW;
                if (sp == 0) { tC = 0.f; break; }
                sp--;
                uint4 a = stk[base + sp];
                tS = __uint_as_float(a.x); tW = __uint_as_float(a.y);
                tC = __uint_as_float(a.z); tSt = (int)a.w;
                tNum = tS - tW;
            }
            if (tC > 0.f) { stk[base + sp] = packAtom(tS, tW, tC, tSt); sp++; }
            tS = cS; tW = cW; tC = cC; tSt = cSt; tNum = cNum;
        }
        stk[base + sp] = packAtom(tS, tW, tC, tSt); sp++;
        cntA[tid] = sp;
    }

    // ---- tree merge: 8 levels of parallel pairwise PAV-list merges ----
    // Merging left+right lists: left's block means strictly decrease, so
    // replaying left onto a stack never pools; streaming right's atoms pools
    // exactly as the serial left-to-right stream would. Hierarchical merge
    // therefore yields the identical final block list.
    uint4* finBuf;
    {
        uint4* srcB = stk;   uint4* dstB = dense;
        int*   sCnt = cntA;  int*   dCnt = cntB;
        int NL = NCHUNK, S = CHUNK;
        while (NL > 1) {
            __syncthreads();
            if (tid < (NL >> 1)) {
                const uint4* L = srcB + (2 * tid) * S;
                const uint4* R = srcB + (2 * tid + 1) * S;
                uint4* D = dstB + tid * (2 * S);
                int la = sCnt[2 * tid], lb = sCnt[2 * tid + 1];
                // copy left list except its last block (held in registers)
                for (int j = 0; j < la - 1; j++) D[j] = L[j];
                uint4 a = L[la - 1];
                float tS = __uint_as_float(a.x), tW = __uint_as_float(a.y);
                float tC = __uint_as_float(a.z);
                int   tSt = (int)a.w;
                float tNum = tS - tW;
                int sp = la - 1;
                for (int r = 0; r < lb; r++) {
                    uint4 b = R[r];
                    float cS = __uint_as_float(b.x), cW = __uint_as_float(b.y);
                    float cC = __uint_as_float(b.z);
                    int   cSt = (int)b.w;
                    float cNum = cS - cW;
                    while (tNum * cC < cNum * tC) {
                        cS += tS; cW += tW; cC += tC; cSt = tSt;
                        cNum = cS - cW;
                        if (sp == 0) { tC = 0.f; break; }
                        sp--;
                        uint4 p = D[sp];
                        tS = __uint_as_float(p.x); tW = __uint_as_float(p.y);
                        tC = __uint_as_float(p.z); tSt = (int)p.w;
                        tNum = tS - tW;
                    }
                    if (tC > 0.f) { D[sp++] = packAtom(tS, tW, tC, tSt); }
                    tS = cS; tW = cW; tC = cC; tSt = cSt; tNum = cNum;
                }
                D[sp++] = packAtom(tS, tW, tC, tSt);
                dCnt[tid] = sp;
            }
            uint4* tb = srcB; srcB = dstB; dstB = tb;
            int*   tc = sCnt; sCnt = dCnt; dCnt = tc;
            NL >>= 1; S <<= 1;
        }
        __syncthreads();
        finBuf = srcB;                       // 8 levels -> back in stk
        if (tid == 0) *nbPtr = sCnt[0];
    }
    __syncthreads();

    const int nb = *nbPtr;
    for (int b = tid; b < nb; b += NTHREADS) {
        uint4 a = finBuf[b];
        fStart[b] = (int)a.w;
        fMean[b]  = (__uint_as_float(a.x) - __uint_as_float(a.y))
                    / __uint_as_float(a.z);
    }
    if (tid == 0) fStart[nb] = N;
    __syncthreads();

    // ---- scatter + own-row moments (rLoc overlays dense; extract done) ----
    float sR = 0.f, sR2 = 0.f;
#pragma unroll
    for (int m = 0; m < 4; m++) {
        int i = tid + m * NTHREADS;
        u64 kk = kArr[i];
        float s = decodeVal((u32)(kk >> 32));
        int  id = (int)(kk & 0xFFFFFFFFu);
        int lo = 0, hi = nb - 1;
        while (lo < hi) {
            int mid = (lo + hi + 1) >> 1;
            if (fStart[mid] <= i) lo = mid; else hi = mid - 1;
        }
        float r = s - fMean[lo] - 2048.5f;     // shift is Spearman-invariant
        g_rank[row][id] = r;
        rLoc[id] = r;
        sR  += r;
        sR2 += r * r;
    }

    float B = 0.f;
    if (row == 1) {
        float4 x4 = ((const float4*)yhat)[tid];
        float4 y4 = ((const float4*)ytar)[tid];
        B += fmaxf(x4.x, 0.f) + log1pf(expf(-fabsf(x4.x))) - x4.x * y4.x;
        B += fmaxf(x4.y, 0.f) + log1pf(expf(-fabsf(x4.y))) - x4.y * y4.y;
        B += fmaxf(x4.z, 0.f) + log1pf(expf(-fabsf(x4.z))) - x4.z * y4.z;
        B += fmaxf(x4.w, 0.f) + log1pf(expf(-fabsf(x4.w))) - x4.w * y4.w;
    }
    blockReduce3(sR, sR2, B, red);
    if (tid == 0) {
        g_sum[row]   = sR;
        g_sumsq[row] = sR2;
        if (row == 1) g_bce = B;
    }

    // ============ gate 2: second of the two row CTAs finishes ============
    __threadfence();
    __syncthreads();
    if (tid == 0) shWho[1] = atomicAdd(&g_cnt2, 1);
    __syncthreads();
    if (shWho[1] != 1) return;
    __threadfence();   // acquire other row's ranks + partials

    {
        const float* other = g_rank[1 - row];
        float cr = 0.f;
#pragma unroll
        for (int m = 0; m < 4; m++) {
            int i = tid + m * NTHREADS;
            cr += other[i] * rLoc[i];
            g_tick[0][i] = 0;            // reset tickets for next replay
            g_tick[1][i] = 0;
        }
        cr = blockReduceSum(cr, red);
        if (tid == 0) {
            float invN = 1.0f / (float)N;
            float mp = g_sum[0] * invN, mt = g_sum[1] * invN;
            float varP = g_sumsq[0] - (float)N * mp * mp;
            float varT = g_sumsq[1] - (float)N * mt * mt;
            float cov  = cr - (float)N * mp * mt;
            float sp   = cov * rsqrtf(varP * varT);
            out[0] = (1.0f - sp) + g_bce * invN;
            g_cnt[0] = 0; g_cnt[1] = 0; g_cnt2 = 0;   // reset for graph replay
        }
    }
}

extern "C" void kernel_launch(void* const* d_in, const int* in_sizes, int n_in,
                              void* d_out, int out_size) {
    const float* yhat = (const float*)d_in[0];
    const float* ytar = (const float*)d_in[1];
    float* out = (float*)d_out;
    cudaFuncSetAttribute(fusedKernel,
                         cudaFuncAttributeMaxDynamicSharedMemorySize, SMEM_BYTES);
    fusedKernel<<<2 * NCTA_ROW, NTHREADS, SMEM_BYTES>>>(yhat, ytar, out);
}